// round 14
// baseline (speedup 1.0000x reference)
#include <cuda_runtime.h>
#include <cstddef>

// ===========================================================================
// mh_attention — exact restructure honoring the literal [16,128]->[4,16,32]
// reshape: slot kk of head h -> (neighbor nb = h*4+(kk>>2), ch-block cb = kk&3)
//
//   q[n]        = Wq x[n] + bq                                   [128]
//   t[n,h,cb]   = q_h . bk[cb*32:+32]
//   r[n,h,cb,:] = Wk[cb*32:+32,:]^T q_h                          [16][128]
//   logit[h,kk] = (nf[n,nb].r[h,cb] + t[h,cb]) / sqrt(128)
//   att         = softmax over the 16 kk slots per head
//   s[h,cb,:]   = sum_a att[h,a*4+cb] * nf[n,h*4+a]
//   out[h*32+d] = sum_cb Wv[cb*32+d,:].s[h,cb] + sum_cb asum[h,cb]*bv[cb*32+d]
// All fp32 via fma.rn.f32x2 -> ~1e-6 of reference.
// ===========================================================================

#define CC    128
#define KK    16
#define HH    4
#define NPAD  132      // padded row: 33x16B (odd) -> conflict-free LDS.128
#define SST   129      // s-phase row stride (quads distinct per (p,h) in a warp)
#define NMAX  100000
#define TP    8        // points per tile (kernel B)
#define GRID_B 148
#define NTHR  256

__device__ float g_q[(size_t)NMAX * CC];   // 51.2 MB scratch

// ---- exact packed-fp32 helpers ----
__device__ __forceinline__ unsigned long long ffma2(unsigned long long a,
                                                    unsigned long long b,
                                                    unsigned long long c) {
    unsigned long long d;
    asm("fma.rn.f32x2 %0, %1, %2, %3;" : "=l"(d) : "l"(a), "l"(b), "l"(c));
    return d;
}
__device__ __forceinline__ float f2sum(unsigned long long a) {
    float lo, hi;
    asm("mov.b64 {%0,%1}, %2;" : "=f"(lo), "=f"(hi) : "l"(a));
    return lo + hi;
}
__device__ __forceinline__ unsigned long long f2pack(float lo, float hi) {
    unsigned long long r;
    asm("mov.b64 %0, {%1,%2};" : "=l"(r) : "f"(lo), "f"(hi));
    return r;
}

// ============================ Kernel A: q projection ========================
#define A_PTS 16
static const size_t SMEM_A_FLOATS = (size_t)CC*NPAD + CC + (size_t)A_PTS*CC;

__global__ __launch_bounds__(NTHR)
void qproj_kernel(const float* __restrict__ x_feat,
                  const float* __restrict__ Wq, const float* __restrict__ bq,
                  int N)
{
    extern __shared__ float sm[];
    float* Wq_s = sm;                 // [128][132]
    float* bq_s = Wq_s + CC*NPAD;     // [128]
    float* xs   = bq_s + CC;          // [16][128]

    const int tid = threadIdx.x;
    for (int idx = tid; idx < CC*CC; idx += NTHR)
        Wq_s[(idx >> 7)*NPAD + (idx & 127)] = Wq[idx];
    if (tid < CC) bq_s[tid] = bq[tid];

    const int base = blockIdx.x * A_PTS;
    #pragma unroll
    for (int i = 0; i < 2; ++i) {                 // stage 16x128 x
        int v = tid + NTHR*i;
        int p = v >> 5, d4 = v & 31;
        int n = base + p; if (n >= N) n = N - 1;
        *(float4*)(xs + p*CC + d4*4) =
            *(const float4*)(x_feat + (size_t)n*CC + d4*4);
    }
    __syncthreads();

    const int c  = tid & 127;
    const int p0 = (tid >> 7) * 8;

    unsigned long long acc[8];
    float b = bq_s[c];
    #pragma unroll
    for (int p = 0; p < 8; ++p) acc[p] = f2pack(b, 0.f);

    const ulonglong2* w2 = (const ulonglong2*)(Wq_s + c*NPAD);
    #pragma unroll 8
    for (int d4 = 0; d4 < 32; ++d4) {
        ulonglong2 w = w2[d4];
        #pragma unroll
        for (int p = 0; p < 8; ++p) {
            ulonglong2 xv = *(const ulonglong2*)(xs + (p0 + p)*CC + d4*4);
            acc[p] = ffma2(w.x, xv.x, acc[p]);
            acc[p] = ffma2(w.y, xv.y, acc[p]);
        }
    }
    #pragma unroll
    for (int p = 0; p < 8; ++p) {
        int n = base + p0 + p;
        if (n < N) g_q[(size_t)n*CC + c] = f2sum(acc[p]);
    }
}

// ======================= Kernel B: persistent fused =========================
static const size_t SMEM_B_FLOATS =
      (size_t)CC*NPAD        // WvR[e][d][cb] (+4 pad)       16896
    + (size_t)TP*KK*NPAD     // nf_s                          16896
    + (size_t)TP*KK*NPAD     // rs (r rows; then s at SST)    16896
    + (size_t)TP*CC          // qs                             1024
    + (size_t)TP*KK          // ts                              128
    + (size_t)TP*HH*KK       // att_s (logits -> att)           512
    + (size_t)TP*HH*HH       // asum_s                          128
    + CC + CC;               // bv_s, bk_s                      256

__global__ __launch_bounds__(NTHR, 1)
void attn_kernel(const float* __restrict__ nfeat, const float* __restrict__ xyz,
                 const float* __restrict__ Wk, const float* __restrict__ Wv,
                 const float* __restrict__ bk, const float* __restrict__ bv,
                 float* __restrict__ out, int N, int ntiles)
{
    extern __shared__ float sm[];
    float* WvR    = sm;
    float* nf_s   = WvR    + CC*NPAD;
    float* rs     = nf_s   + (size_t)TP*KK*NPAD;   // r rows; then s[ph][e][cb] @SST
    float* qs     = rs     + (size_t)TP*KK*NPAD;
    float* ts     = qs     + TP*CC;
    float* att_s  = ts     + TP*KK;
    float* asum_s = att_s  + TP*HH*KK;
    float* bv_s   = asum_s + TP*HH*HH;
    float* bk_s   = bv_s   + CC;

    const int tid = threadIdx.x;
    const int e   = tid & 127;
    const int z   = tid >> 7;

    // WvR[e][d][cb] = Wv[(cb*32+d)*128 + e]
    for (int idx = tid; idx < CC*CC; idx += NTHR) {
        int m = idx >> 7, ee = idx & 127;
        WvR[ee*NPAD + (m & 31)*4 + (m >> 5)] = Wv[idx];
    }
    if (tid < CC) { bv_s[tid] = bv[tid]; bk_s[tid] = bk[tid]; }

    // Wk -> registers: thread (e,z) owns Wk[c][e] for c in [z*64, z*64+64)
    unsigned long long wk2[2][16];
    #pragma unroll
    for (int cbl = 0; cbl < 2; ++cbl) {
        int cb = 2*z + cbl;
        #pragma unroll
        for (int d2 = 0; d2 < 16; ++d2) {
            int c = cb*32 + 2*d2;
            wk2[cbl][d2] = f2pack(Wk[(size_t)c*CC + e],
                                  Wk[(size_t)(c + 1)*CC + e]);
        }
    }

    // cp.async new_feature into nf_s (raw; xyz added at merge via transient LDG)
    auto prefetch = [&](int tile_) {
        int b16 = tile_ * (TP * KK);
        #pragma unroll
        for (int i = 0; i < 16; ++i) {
            int v = tid + NTHR*i;                 // 0..4095 float4 chunks
            int pj = v >> 5, e4 = v & 31;
            long long gj = (long long)b16 + pj;
            if (gj >= (long long)N * KK) gj = (long long)N * KK - 1;
            const float* src = nfeat + (size_t)gj*CC + e4*4;
            unsigned dst = (unsigned)__cvta_generic_to_shared(nf_s + pj*NPAD + e4*4);
            asm volatile("cp.async.cg.shared.global [%0], [%1], 16;"
                         :: "r"(dst), "l"(src) : "memory");
        }
        asm volatile("cp.async.commit_group;" ::: "memory");
    };

    int tile = blockIdx.x;
    if (tile < ntiles) prefetch(tile);
    __syncthreads();   // WvR / bv / bk visible

    for (; tile < ntiles; tile += GRID_B) {
        const int base = tile * TP;

        // ---- merge nf += xyz (transient LDG batch; regs freed before compute)
        {
            float4 tmp[16];
            int b16 = tile * (TP * KK);
            #pragma unroll
            for (int i = 0; i < 16; ++i) {
                int v = tid + NTHR*i;
                int pj = v >> 5, e4 = v & 31;
                long long gj = (long long)b16 + pj;
                if (gj >= (long long)N * KK) gj = (long long)N * KK - 1;
                tmp[i] = *(const float4*)(xyz + (size_t)gj*CC + e4*4);
            }
            asm volatile("cp.async.wait_group 0;" ::: "memory");
            #pragma unroll
            for (int i = 0; i < 16; ++i) {
                int v = tid + NTHR*i;
                int pj = v >> 5, e4 = v & 31;
                float4* d = (float4*)(nf_s + pj*NPAD + e4*4);
                float4 cur = *d;
                cur.x += tmp[i].x; cur.y += tmp[i].y;
                cur.z += tmp[i].z; cur.w += tmp[i].w;
                *d = cur;
            }
        }
        // ---- stage q ----
        {
            int p = tid >> 5, d4 = tid & 31;
            int n = base + p; if (n >= N) n = N - 1;
            *(float4*)(qs + p*CC + d4*4) =
                *(const float4*)(g_q + (size_t)n*CC + d4*4);
        }
        __syncthreads();

        // ---- R phase: r[p][h*4+cb][e], thread owns cb in {2z, 2z+1} ----
        #pragma unroll 1
        for (int p = 0; p < TP; ++p) {
            unsigned long long racc[HH][2];
            #pragma unroll
            for (int h = 0; h < HH; ++h) { racc[h][0] = 0ull; racc[h][1] = 0ull; }
            #pragma unroll
            for (int d4 = 0; d4 < 8; ++d4) {
                #pragma unroll
                for (int h = 0; h < HH; ++h) {
                    ulonglong2 qv = *(const ulonglong2*)(qs + p*CC + h*32 + d4*4);
                    racc[h][0] = ffma2(wk2[0][2*d4],     qv.x, racc[h][0]);
                    racc[h][0] = ffma2(wk2[0][2*d4 + 1], qv.y, racc[h][0]);
                    racc[h][1] = ffma2(wk2[1][2*d4],     qv.x, racc[h][1]);
                    racc[h][1] = ffma2(wk2[1][2*d4 + 1], qv.y, racc[h][1]);
                }
            }
            #pragma unroll
            for (int h = 0; h < HH; ++h) {
                rs[(p*KK + h*4 + 2*z    )*NPAD + e] = f2sum(racc[h][0]);
                rs[(p*KK + h*4 + 2*z + 1)*NPAD + e] = f2sum(racc[h][1]);
            }
        }
        // ---- t[p][h*4+cb] = q_h . bk_cb ----
        if (tid < 128) {
            int p = tid >> 4, g = tid & 15, h = g >> 2, cb = g & 3;
            unsigned long long ta = 0ull;
            #pragma unroll
            for (int d4 = 0; d4 < 8; ++d4) {
                ulonglong2 qv = *(const ulonglong2*)(qs + p*CC + h*32 + d4*4);
                ulonglong2 bb = *(const ulonglong2*)(bk_s + cb*32 + d4*4);
                ta = ffma2(qv.x, bb.x, ta);
                ta = ffma2(qv.y, bb.y, ta);
            }
            ts[p*KK + g] = f2sum(ta);
        }
        __syncthreads();

        // ---- L phase: 512 logits, 2 per thread ----
        #pragma unroll
        for (int rep = 0; rep < 2; ++rep) {
            int idx = tid + rep*NTHR;
            int cb = idx & 3, nb = (idx >> 2) & 15, p = idx >> 6;
            int h = nb >> 2, a = nb & 3;
            const float* nfr = nf_s + (p*KK + nb)*NPAD;
            const float* rr  = rs   + (p*KK + h*4 + cb)*NPAD;
            unsigned long long da = 0ull, db = 0ull;
            #pragma unroll 8
            for (int i4 = 0; i4 < 32; ++i4) {
                ulonglong2 nv = *(const ulonglong2*)(nfr + i4*4);
                ulonglong2 rv = *(const ulonglong2*)(rr  + i4*4);
                da = ffma2(nv.x, rv.x, da);
                db = ffma2(nv.y, rv.y, db);
            }
            float lg = (f2sum(da) + f2sum(db) + ts[p*KK + h*4 + cb])
                     * 0.08838834764831845f;     // 1/sqrt(128)
            att_s[(p*HH + h)*KK + a*4 + cb] = lg;
        }
        __syncthreads();

        // ---- softmax over 16 slots per (p,h); asum[p][h][cb] ----
        {
            int kk = tid & 15, gi = tid >> 4;
            #pragma unroll
            for (int rep = 0; rep < 2; ++rep) {
                int ph = gi + rep*16;                  // p*4+h, 0..31
                float l = att_s[ph*KK + kk];
                float mx = l;
                #pragma unroll
                for (int o = 1; o < 16; o <<= 1)
                    mx = fmaxf(mx, __shfl_xor_sync(0xffffffffu, mx, o));
                float ev = __expf(l - mx);
                float sme = ev;
                #pragma unroll
                for (int o = 1; o < 16; o <<= 1)
                    sme += __shfl_xor_sync(0xffffffffu, sme, o);
                float av = ev / sme;
                att_s[ph*KK + kk] = av;
                float as = av + __shfl_xor_sync(0xffffffffu, av, 4);
                as += __shfl_xor_sync(0xffffffffu, as, 8);
                if (kk < 4) asum_s[ph*4 + kk] = as;
            }
        }
        __syncthreads();

        // ---- S phase: s[ph][e][cb] @ stride SST; sum_a att*nf ----
        #pragma unroll 1
        for (int pl = 0; pl < 4; ++pl) {
            int p = z*4 + pl;
            #pragma unroll
            for (int h = 0; h < HH; ++h) {
                unsigned long long s01 = 0ull, s23 = 0ull;
                const float* ab = att_s + (p*HH + h)*KK;
                #pragma unroll
                for (int a = 0; a < 4; ++a) {
                    float nv = nf_s[(p*KK + h*4 + a)*NPAD + e];
                    unsigned long long nn = f2pack(nv, nv);
                    ulonglong2 at = *(const ulonglong2*)(ab + a*4);
                    s01 = ffma2(at.x, nn, s01);
                    s23 = ffma2(at.y, nn, s23);
                }
                ulonglong2 sv; sv.x = s01; sv.y = s23;
                *(ulonglong2*)(rs + ((p*HH + h)*SST + e)*4) = sv;
            }
        }
        __syncthreads();

        // ---- issue next-tile nf prefetch (hides under OUT) ----
        {
            int nxt = tile + GRID_B;
            if (nxt < ntiles) prefetch(nxt);
        }

        // ---- OUT phase: 2p x 2d register tile ----
        {
            const int d16 = tid & 15;
            const int h   = (tid >> 4) & 3;
            const int pq  = tid >> 6;            // 0..3
            const int pA  = 2*pq, pB = 2*pq + 1;
            const float* wv0p = WvR + d16*4;
            const float* wv1p = WvR + (d16 + 16)*4;
            const float* svA  = rs + (pA*HH + h)*SST*4;
            const float* svB  = rs + (pB*HH + h)*SST*4;
            unsigned long long aA0x=0, aA0y=0, aA1x=0, aA1y=0;
            unsigned long long aB0x=0, aB0y=0, aB1x=0, aB1y=0;
            #pragma unroll 4
            for (int ee = 0; ee < CC; ++ee) {
                ulonglong2 w0 = *(const ulonglong2*)(wv0p + ee*NPAD);
                ulonglong2 w1 = *(const ulonglong2*)(wv1p + ee*NPAD);
                ulonglong2 sA = *(const ulonglong2*)(svA + ee*4);
                ulonglong2 sB = *(const ulonglong2*)(svB + ee*4);
                aA0x = ffma2(w0.x, sA.x, aA0x); aA0y = ffma2(w0.y, sA.y, aA0y);
                aA1x = ffma2(w1.x, sA.x, aA1x); aA1y = ffma2(w1.y, sA.y, aA1y);
                aB0x = ffma2(w0.x, sB.x, aB0x); aB0y = ffma2(w0.y, sB.y, aB0y);
                aB1x = ffma2(w1.x, sB.x, aB1x); aB1y = ffma2(w1.y, sB.y, aB1y);
            }
            float bva0 = bv_s[d16],      bva1 = bv_s[32 + d16],
                  bva2 = bv_s[64 + d16], bva3 = bv_s[96 + d16];
            float bvb0 = bv_s[16 + d16],      bvb1 = bv_s[48 + d16],
                  bvb2 = bv_s[80 + d16],      bvb3 = bv_s[112 + d16];
            float4 uA = *(const float4*)(asum_s + (pA*HH + h)*4);
            float4 uB = *(const float4*)(asum_s + (pB*HH + h)*4);
            float oA0 = f2sum(aA0x) + f2sum(aA0y)
                      + uA.x*bva0 + uA.y*bva1 + uA.z*bva2 + uA.w*bva3;
            float oA1 = f2sum(aA1x) + f2sum(aA1y)
                      + uA.x*bvb0 + uA.y*bvb1 + uA.z*bvb2 + uA.w*bvb3;
            float oB0 = f2sum(aB0x) + f2sum(aB0y)
                      + uB.x*bva0 + uB.y*bva1 + uB.z*bva2 + uB.w*bva3;
            float oB1 = f2sum(aB1x) + f2sum(aB1y)
                      + uB.x*bvb0 + uB.y*bvb1 + uB.z*bvb2 + uB.w*bvb3;
            int nA = base + pA, nB = base + pB;
            int m0 = h*32 + d16, m1 = m0 + 16;
            if (nA < N) {
                out[(size_t)nA*CC + m0] = oA0;
                out[(size_t)nA*CC + m1] = oA1;
            }
            if (nB < N) {
                out[(size_t)nB*CC + m0] = oB0;
                out[(size_t)nB*CC + m1] = oB1;
            }
        }
        __syncthreads();
    }
}

// ================================ launch ====================================
extern "C" void kernel_launch(void* const* d_in, const int* in_sizes, int n_in,
                              void* d_out, int out_size)
{
    // order: x_feat, xyz_enc, new_feature, head, d_k, Wq, bq, Wk, bk, Wv, bv
    const float* x_feat = (const float*)d_in[0];
    const float* xyz    = (const float*)d_in[1];
    const float* nfeat  = (const float*)d_in[2];
    const float* Wq     = (const float*)d_in[5];
    const float* bq     = (const float*)d_in[6];
    const float* Wk     = (const float*)d_in[7];
    const float* bk     = (const float*)d_in[8];
    const float* Wv     = (const float*)d_in[9];
    const float* bv     = (const float*)d_in[10];
    float* out = (float*)d_out;

    int N = in_sizes[0] / CC;
    if (N > NMAX) N = NMAX;

    const int smA = (int)(SMEM_A_FLOATS * sizeof(float));
    const int smB = (int)(SMEM_B_FLOATS * sizeof(float));
    cudaFuncSetAttribute(qproj_kernel, cudaFuncAttributeMaxDynamicSharedMemorySize, smA);
    cudaFuncSetAttribute(attn_kernel,  cudaFuncAttributeMaxDynamicSharedMemorySize, smB);

    int ntiles = (N + TP - 1) / TP;
    int gridA  = (N + A_PTS - 1) / A_PTS;
    int gridB  = ntiles < GRID_B ? ntiles : GRID_B;

    qproj_kernel<<<gridA, NTHR, smA>>>(x_feat, Wq, bq, N);
    attn_kernel<<<gridB, NTHR, smB>>>(nfeat, xyz, Wk, Wv, bk, bv, out, N, ntiles);
}

// round 15
// speedup vs baseline: 1.0715x; 1.0715x over previous
#include <cuda_runtime.h>
#include <cstddef>

// ===========================================================================
// mh_attention — exact restructure honoring the literal [16,128]->[4,16,32]
// reshape: slot kk of head h -> (neighbor nb = h*4+(kk>>2), ch-block cb = kk&3)
//
//   q[n]        = Wq x[n] + bq                                   [128]
//   t[n,h,cb]   = q_h . bk[cb*32:+32]
//   r[n,h,cb,:] = Wk[cb*32:+32,:]^T q_h                          [16][128]
//   logit[h,kk] = (nf[n,nb].r[h,cb] + t[h,cb]) / sqrt(128)
//   att         = softmax over the 16 kk slots per head
//   s[h,cb,:]   = sum_a att[h,a*4+cb] * nf[n,h*4+a]
//   out[h*32+d] = sum_cb Wv[cb*32+d,:].s[h,cb] + sum_cb asum[h,cb]*bv[cb*32+d]
// All fp32 via fma.rn.f32x2 -> ~1e-6 of reference.
// ===========================================================================

#define CC    128
#define KK    16
#define HH    4
#define NPAD  132      // padded row: 33x16B (odd) -> conflict-free LDS.128
#define SST   129      // s row stride (16B units distinct per (p,h))
#define PST   36       // partial-sum row stride (quad stride 9 -> distinct)
#define NMAX  100000
#define TP    8        // points per tile (kernel B)
#define GRID_B 148
#define NTHR  256

__device__ float g_q[(size_t)NMAX * CC];   // 51.2 MB scratch

// ---- exact packed-fp32 helpers ----
__device__ __forceinline__ unsigned long long ffma2(unsigned long long a,
                                                    unsigned long long b,
                                                    unsigned long long c) {
    unsigned long long d;
    asm("fma.rn.f32x2 %0, %1, %2, %3;" : "=l"(d) : "l"(a), "l"(b), "l"(c));
    return d;
}
__device__ __forceinline__ float f2sum(unsigned long long a) {
    float lo, hi;
    asm("mov.b64 {%0,%1}, %2;" : "=f"(lo), "=f"(hi) : "l"(a));
    return lo + hi;
}
__device__ __forceinline__ unsigned long long f2pack(float lo, float hi) {
    unsigned long long r;
    asm("mov.b64 %0, {%1,%2};" : "=l"(r) : "f"(lo), "f"(hi));
    return r;
}

// ============================ Kernel A: q projection ========================
#define A_PTS 16
static const size_t SMEM_A_FLOATS = (size_t)CC*NPAD + CC + (size_t)A_PTS*CC;

__global__ __launch_bounds__(NTHR)
void qproj_kernel(const float* __restrict__ x_feat,
                  const float* __restrict__ Wq, const float* __restrict__ bq,
                  int N)
{
    extern __shared__ float sm[];
    float* Wq_s = sm;                 // [128][132]
    float* bq_s = Wq_s + CC*NPAD;     // [128]
    float* xs   = bq_s + CC;          // [16][128]

    const int tid = threadIdx.x;
    for (int idx = tid; idx < CC*CC; idx += NTHR)
        Wq_s[(idx >> 7)*NPAD + (idx & 127)] = Wq[idx];
    if (tid < CC) bq_s[tid] = bq[tid];

    const int base = blockIdx.x * A_PTS;
    #pragma unroll
    for (int i = 0; i < 2; ++i) {                 // stage 16x128 x
        int v = tid + NTHR*i;
        int p = v >> 5, d4 = v & 31;
        int n = base + p; if (n >= N) n = N - 1;
        *(float4*)(xs + p*CC + d4*4) =
            *(const float4*)(x_feat + (size_t)n*CC + d4*4);
    }
    __syncthreads();

    const int c  = tid & 127;
    const int p0 = (tid >> 7) * 8;

    unsigned long long acc[8];
    float b = bq_s[c];
    #pragma unroll
    for (int p = 0; p < 8; ++p) acc[p] = f2pack(b, 0.f);

    const ulonglong2* w2 = (const ulonglong2*)(Wq_s + c*NPAD);
    #pragma unroll 8
    for (int d4 = 0; d4 < 32; ++d4) {
        ulonglong2 w = w2[d4];
        #pragma unroll
        for (int p = 0; p < 8; ++p) {
            ulonglong2 xv = *(const ulonglong2*)(xs + (p0 + p)*CC + d4*4);
            acc[p] = ffma2(w.x, xv.x, acc[p]);
            acc[p] = ffma2(w.y, xv.y, acc[p]);
        }
    }
    #pragma unroll
    for (int p = 0; p < 8; ++p) {
        int n = base + p0 + p;
        if (n < N) g_q[(size_t)n*CC + c] = f2sum(acc[p]);
    }
}

// ======================= Kernel B: persistent fused =========================
static const size_t SMEM_B_FLOATS =
      (size_t)CC*NPAD        // WvR[e][d][cb]                 16896
    + (size_t)TP*KK*NPAD     // nf_s                          16896
    + (size_t)TP*KK*NPAD     // rs (r rows; then s at SST)    16896
    + (size_t)TP*CC          // qs                             1024
    + (size_t)TP*KK          // ts                              128
    + (size_t)TP*HH*KK       // att_s (logits -> att)           512
    + (size_t)TP*HH*HH       // asum_s                          128
    + CC + CC                // bv_s, bk_s                      256
    + (size_t)2*32*PST;      // part2 (OUT e-split partials)   2304

__global__ __launch_bounds__(NTHR, 1)
void attn_kernel(const float* __restrict__ nfeat, const float* __restrict__ xyz,
                 const float* __restrict__ Wk, const float* __restrict__ Wv,
                 const float* __restrict__ bk, const float* __restrict__ bv,
                 float* __restrict__ out, int N, int ntiles)
{
    extern __shared__ float sm[];
    float* WvR    = sm;
    float* nf_s   = WvR    + CC*NPAD;
    float* rs     = nf_s   + (size_t)TP*KK*NPAD;   // r rows; then s[ph][e][cb] @SST
    float* qs     = rs     + (size_t)TP*KK*NPAD;
    float* ts     = qs     + TP*CC;
    float* att_s  = ts     + TP*KK;
    float* asum_s = att_s  + TP*HH*KK;
    float* bv_s   = asum_s + TP*HH*HH;
    float* bk_s   = bv_s   + CC;
    float* part2  = bk_s   + CC;                   // [2][32][PST]

    const int tid = threadIdx.x;
    const int e   = tid & 127;
    const int z   = tid >> 7;

    // WvR[e][d][cb] = Wv[(cb*32+d)*128 + e]
    for (int idx = tid; idx < CC*CC; idx += NTHR) {
        int m = idx >> 7, ee = idx & 127;
        WvR[ee*NPAD + (m & 31)*4 + (m >> 5)] = Wv[idx];
    }
    if (tid < CC) { bv_s[tid] = bv[tid]; bk_s[tid] = bk[tid]; }

    // Wk -> registers: thread (e,z) owns Wk[c][e] for c in [z*64, z*64+64)
    unsigned long long wk2[2][16];
    #pragma unroll
    for (int cbl = 0; cbl < 2; ++cbl) {
        int cb = 2*z + cbl;
        #pragma unroll
        for (int d2 = 0; d2 < 16; ++d2) {
            int c = cb*32 + 2*d2;
            wk2[cbl][d2] = f2pack(Wk[(size_t)c*CC + e],
                                  Wk[(size_t)(c + 1)*CC + e]);
        }
    }

    // cp.async new_feature into nf_s (raw; xyz added at merge via transient LDG)
    auto prefetch = [&](int tile_) {
        int b16 = tile_ * (TP * KK);
        #pragma unroll
        for (int i = 0; i < 16; ++i) {
            int v = tid + NTHR*i;                 // 0..4095 float4 chunks
            int pj = v >> 5, e4 = v & 31;
            long long gj = (long long)b16 + pj;
            if (gj >= (long long)N * KK) gj = (long long)N * KK - 1;
            const float* src = nfeat + (size_t)gj*CC + e4*4;
            unsigned dst = (unsigned)__cvta_generic_to_shared(nf_s + pj*NPAD + e4*4);
            asm volatile("cp.async.cg.shared.global [%0], [%1], 16;"
                         :: "r"(dst), "l"(src) : "memory");
        }
        asm volatile("cp.async.commit_group;" ::: "memory");
    };

    int tile = blockIdx.x;
    if (tile < ntiles) prefetch(tile);
    __syncthreads();   // WvR / bv / bk visible

    for (; tile < ntiles; tile += GRID_B) {
        const int base = tile * TP;

        // ---- merge nf += xyz (transient LDG batch) ----
        {
            float4 tmp[16];
            int b16 = tile * (TP * KK);
            #pragma unroll
            for (int i = 0; i < 16; ++i) {
                int v = tid + NTHR*i;
                int pj = v >> 5, e4 = v & 31;
                long long gj = (long long)b16 + pj;
                if (gj >= (long long)N * KK) gj = (long long)N * KK - 1;
                tmp[i] = *(const float4*)(xyz + (size_t)gj*CC + e4*4);
            }
            asm volatile("cp.async.wait_group 0;" ::: "memory");
            #pragma unroll
            for (int i = 0; i < 16; ++i) {
                int v = tid + NTHR*i;
                int pj = v >> 5, e4 = v & 31;
                float4* d = (float4*)(nf_s + pj*NPAD + e4*4);
                float4 cur = *d;
                cur.x += tmp[i].x; cur.y += tmp[i].y;
                cur.z += tmp[i].z; cur.w += tmp[i].w;
                *d = cur;
            }
        }
        // ---- stage q ----
        {
            int p = tid >> 5, d4 = tid & 31;
            int n = base + p; if (n >= N) n = N - 1;
            *(float4*)(qs + p*CC + d4*4) =
                *(const float4*)(g_q + (size_t)n*CC + d4*4);
        }
        __syncthreads();

        // ---- R phase: r[p][h*4+cb][e], thread owns cb in {2z, 2z+1} ----
        #pragma unroll 1
        for (int p = 0; p < TP; ++p) {
            unsigned long long racc[HH][2];
            #pragma unroll
            for (int h = 0; h < HH; ++h) { racc[h][0] = 0ull; racc[h][1] = 0ull; }
            #pragma unroll
            for (int d4 = 0; d4 < 8; ++d4) {
                #pragma unroll
                for (int h = 0; h < HH; ++h) {
                    ulonglong2 qv = *(const ulonglong2*)(qs + p*CC + h*32 + d4*4);
                    racc[h][0] = ffma2(wk2[0][2*d4],     qv.x, racc[h][0]);
                    racc[h][0] = ffma2(wk2[0][2*d4 + 1], qv.y, racc[h][0]);
                    racc[h][1] = ffma2(wk2[1][2*d4],     qv.x, racc[h][1]);
                    racc[h][1] = ffma2(wk2[1][2*d4 + 1], qv.y, racc[h][1]);
                }
            }
            #pragma unroll
            for (int h = 0; h < HH; ++h) {
                rs[(p*KK + h*4 + 2*z    )*NPAD + e] = f2sum(racc[h][0]);
                rs[(p*KK + h*4 + 2*z + 1)*NPAD + e] = f2sum(racc[h][1]);
            }
        }
        // ---- t[p][h*4+cb] = q_h . bk_cb ----
        if (tid < 128) {
            int p = tid >> 4, g = tid & 15, h = g >> 2, cb = g & 3;
            unsigned long long ta = 0ull;
            #pragma unroll
            for (int d4 = 0; d4 < 8; ++d4) {
                ulonglong2 qv = *(const ulonglong2*)(qs + p*CC + h*32 + d4*4);
                ulonglong2 bb = *(const ulonglong2*)(bk_s + cb*32 + d4*4);
                ta = ffma2(qv.x, bb.x, ta);
                ta = ffma2(qv.y, bb.y, ta);
            }
            ts[p*KK + g] = f2sum(ta);
        }
        __syncthreads();

        // ---- L phase: 512 logits, 2 per thread ----
        #pragma unroll
        for (int rep = 0; rep < 2; ++rep) {
            int idx = tid + rep*NTHR;
            int cb = idx & 3, nb = (idx >> 2) & 15, p = idx >> 6;
            int h = nb >> 2, a = nb & 3;
            const float* nfr = nf_s + (p*KK + nb)*NPAD;
            const float* rr  = rs   + (p*KK + h*4 + cb)*NPAD;
            unsigned long long da = 0ull, db = 0ull;
            #pragma unroll 8
            for (int i4 = 0; i4 < 32; ++i4) {
                ulonglong2 nv = *(const ulonglong2*)(nfr + i4*4);
                ulonglong2 rv = *(const ulonglong2*)(rr  + i4*4);
                da = ffma2(nv.x, rv.x, da);
                db = ffma2(nv.y, rv.y, db);
            }
            float lg = (f2sum(da) + f2sum(db) + ts[p*KK + h*4 + cb])
                     * 0.08838834764831845f;     // 1/sqrt(128)
            att_s[(p*HH + h)*KK + a*4 + cb] = lg;
        }
        __syncthreads();

        // ---- softmax over 16 slots per (p,h); asum[p][h][cb] ----
        {
            int kk = tid & 15, gi = tid >> 4;
            #pragma unroll
            for (int rep = 0; rep < 2; ++rep) {
                int ph = gi + rep*16;                  // p*4+h, 0..31
                float l = att_s[ph*KK + kk];
                float mx = l;
                #pragma unroll
                for (int o = 1; o < 16; o <<= 1)
                    mx = fmaxf(mx, __shfl_xor_sync(0xffffffffu, mx, o));
                float ev = __expf(l - mx);
                float sme = ev;
                #pragma unroll
                for (int o = 1; o < 16; o <<= 1)
                    sme += __shfl_xor_sync(0xffffffffu, sme, o);
                float av = ev / sme;
                att_s[ph*KK + kk] = av;
                float as = av + __shfl_xor_sync(0xffffffffu, av, 4);
                as += __shfl_xor_sync(0xffffffffu, as, 8);
                if (kk < 4) asum_s[ph*4 + kk] = as;
            }
        }
        __syncthreads();

        // ---- S phase: s[ph][e][cb] @ stride SST; sum_a att*nf ----
        #pragma unroll 1
        for (int pl = 0; pl < 4; ++pl) {
            int p = z*4 + pl;
            #pragma unroll
            for (int h = 0; h < HH; ++h) {
                unsigned long long s01 = 0ull, s23 = 0ull;
                const float* ab = att_s + (p*HH + h)*KK;
                #pragma unroll
                for (int a = 0; a < 4; ++a) {
                    float nv = nf_s[(p*KK + h*4 + a)*NPAD + e];
                    unsigned long long nn = f2pack(nv, nv);
                    ulonglong2 at = *(const ulonglong2*)(ab + a*4);
                    s01 = ffma2(at.x, nn, s01);
                    s23 = ffma2(at.y, nn, s23);
                }
                ulonglong2 sv; sv.x = s01; sv.y = s23;
                *(ulonglong2*)(rs + ((p*HH + h)*SST + e)*4) = sv;
            }
        }
        __syncthreads();

        // ---- issue next-tile nf prefetch (hides under OUT) ----
        {
            int nxt = tile + GRID_B;
            if (nxt < ntiles) prefetch(nxt);
        }

        // ---- OUT phase: e-split; warp = 8 dd x 4 phq, thread = 4d x 2ph ----
        {
            const int lane = tid & 31;
            const int w    = tid >> 5;
            const int dd   = lane & 7;            // 0..7
            const int phq  = lane >> 3;           // 0..3
            const int eh   = w & 1;               // e-half
            const int pg   = w >> 1;              // 0..3 (ph octet)
            const int ph0  = pg*8 + phq;
            const int ph1  = ph0 + 4;
            const float* wb = WvR + dd*4;
            const float* sA = rs + ph0*SST*4;
            const float* sB = rs + ph1*SST*4;
            unsigned long long aA[4][2], aB[4][2];
            #pragma unroll
            for (int k = 0; k < 4; ++k) {
                aA[k][0] = 0ull; aA[k][1] = 0ull;
                aB[k][0] = 0ull; aB[k][1] = 0ull;
            }
            const int ebeg = eh*64;
            #pragma unroll 4
            for (int ee = ebeg; ee < ebeg + 64; ++ee) {
                ulonglong2 sva = *(const ulonglong2*)(sA + ee*4);
                ulonglong2 svb = *(const ulonglong2*)(sB + ee*4);
                #pragma unroll
                for (int k = 0; k < 4; ++k) {
                    ulonglong2 wv = *(const ulonglong2*)(wb + ee*NPAD + k*32);
                    aA[k][0] = ffma2(wv.x, sva.x, aA[k][0]);
                    aA[k][1] = ffma2(wv.y, sva.y, aA[k][1]);
                    aB[k][0] = ffma2(wv.x, svb.x, aB[k][0]);
                    aB[k][1] = ffma2(wv.y, svb.y, aB[k][1]);
                }
            }
            #pragma unroll
            for (int k = 0; k < 4; ++k) {
                int d = dd + 8*k;
                part2[(eh*32 + ph0)*PST + d] = f2sum(aA[k][0]) + f2sum(aA[k][1]);
                part2[(eh*32 + ph1)*PST + d] = f2sum(aB[k][0]) + f2sum(aB[k][1]);
            }
        }
        __syncthreads();

        // ---- combine halves + bias + coalesced STG.128 ----
        {
            int ph = tid >> 3, dq = tid & 7, d0 = dq*4;
            int p = ph >> 2, h = ph & 3;
            float4 v0 = *(const float4*)(part2 + ph*PST + d0);
            float4 v1 = *(const float4*)(part2 + (32 + ph)*PST + d0);
            float4 u  = *(const float4*)(asum_s + ph*4);
            float4 b0 = *(const float4*)(bv_s +      d0);
            float4 b1 = *(const float4*)(bv_s + 32 + d0);
            float4 b2 = *(const float4*)(bv_s + 64 + d0);
            float4 b3 = *(const float4*)(bv_s + 96 + d0);
            float4 o;
            o.x = v0.x + v1.x + u.x*b0.x + u.y*b1.x + u.z*b2.x + u.w*b3.x;
            o.y = v0.y + v1.y + u.x*b0.y + u.y*b1.y + u.z*b2.y + u.w*b3.y;
            o.z = v0.z + v1.z + u.x*b0.z + u.y*b1.z + u.z*b2.z + u.w*b3.z;
            o.w = v0.w + v1.w + u.x*b0.w + u.y*b1.w + u.z*b2.w + u.w*b3.w;
            int n = base + p;
            if (n < N) *(float4*)(out + (size_t)n*CC + h*32 + d0) = o;
        }
        __syncthreads();
    }
}

// ================================ launch ====================================
extern "C" void kernel_launch(void* const* d_in, const int* in_sizes, int n_in,
                              void* d_out, int out_size)
{
    // order: x_feat, xyz_enc, new_feature, head, d_k, Wq, bq, Wk, bk, Wv, bv
    const float* x_feat = (const float*)d_in[0];
    const float* xyz    = (const float*)d_in[1];
    const float* nfeat  = (const float*)d_in[2];
    const float* Wq     = (const float*)d_in[5];
    const float* bq     = (const float*)d_in[6];
    const float* Wk     = (const float*)d_in[7];
    const float* bk     = (const float*)d_in[8];
    const float* Wv     = (const float*)d_in[9];
    const float* bv     = (const float*)d_in[10];
    float* out = (float*)d_out;

    int N = in_sizes[0] / CC;
    if (N > NMAX) N = NMAX;

    const int smA = (int)(SMEM_A_FLOATS * sizeof(float));
    const int smB = (int)(SMEM_B_FLOATS * sizeof(float));
    cudaFuncSetAttribute(qproj_kernel, cudaFuncAttributeMaxDynamicSharedMemorySize, smA);
    cudaFuncSetAttribute(attn_kernel,  cudaFuncAttributeMaxDynamicSharedMemorySize, smB);

    int ntiles = (N + TP - 1) / TP;
    int gridA  = (N + A_PTS - 1) / A_PTS;
    int gridB  = ntiles < GRID_B ? ntiles : GRID_B;

    qproj_kernel<<<gridA, NTHR, smA>>>(x_feat, Wq, bq, N);
    attn_kernel<<<gridB, NTHR, smB>>>(nfeat, xyz, Wk, Wv, bk, bv, out, N, ntiles);
}